// round 12
// baseline (speedup 1.0000x reference)
#include <cuda_runtime.h>
#include <cuda_fp16.h>
#include <cstdint>

// Shapes (fixed)
#define BB 256
#define SS 512
#define FF 64
#define HH 1024

#define NCTA 256    // 2 batch-groups x 128 hidden-blocks
#define NTHR 256    // 8 warps: 4 m-groups x 2 k-split
#define MB 128
#define NH 8
#define GT 32       // gate rows per CTA = 4*NH
#define KC 32       // K chunk
#define KTOT (HH + FF)          // 1088
#define NCHUNK (KTOT / KC)      // 34
#define NSTG 4

#define WST 1096    // weight smem row stride (halves)
#define GST 36      // gate buffer row stride (floats)

#define WBYTES (GT * WST * 2)           // 70144
#define ASLOT 2560                      // 32 rows x 80B (conflict-free ldsm)
#define AGRP (NSTG * ASLOT)             // 10240 per m-group
#define ABYTES (4 * AGRP)               // 40960
#define AOFF WBYTES
#define GS2OFF (AOFF + MB * GST * 4)    // second gate buffer
#define CTRL (WBYTES + ABYTES)          // 111104
#define SMEM_BYTES (CTRL + 256)         // 111360 -> 2 CTAs/SM fit

// Persistent state (no allocations allowed)
__device__ __half g_h[2][BB * HH];
__device__ float  g_c[BB * HH];
__device__ __half g_x[BB * FF];
__device__ __half g_xs[BB * SS * FF];
__device__ unsigned g_bar_cnt[2];
__device__ unsigned g_bar_gen[2];

// per-group grid barrier (128 CTAs each; groups fully independent)
__device__ __forceinline__ void grid_barrier(int grp) {
    __syncthreads();
    if (threadIdx.x == 0) {
        __threadfence();
        unsigned gen = *(volatile unsigned*)&g_bar_gen[grp];
        if (atomicAdd(&g_bar_cnt[grp], 1u) == 127u) {
            atomicExch(&g_bar_cnt[grp], 0u);
            __threadfence();
            atomicAdd(&g_bar_gen[grp], 1u);
        } else {
            while (*(volatile unsigned*)&g_bar_gen[grp] == gen) { }
        }
        __threadfence();
    }
    __syncthreads();
}

__device__ __forceinline__ float sigm(float x) { return 1.0f / (1.0f + __expf(-x)); }
__device__ __forceinline__ float tanh_f(float x) {
    float xx = fminf(fmaxf(x, -15.0f), 15.0f);
    float e = __expf(2.0f * xx);
    return (e - 1.0f) / (e + 1.0f);
}
__device__ __forceinline__ void cpa16(uint32_t s, const void* g) {
    asm volatile("cp.async.cg.shared.global [%0], [%1], 16;" :: "r"(s), "l"(g));
}
#define CP_COMMIT() asm volatile("cp.async.commit_group;" ::: "memory")
__device__ __forceinline__ void ldsm4(uint32_t r[4], uint32_t a) {
    asm volatile("ldmatrix.sync.aligned.m8n8.x4.shared.b16 {%0,%1,%2,%3}, [%4];"
                 : "=r"(r[0]), "=r"(r[1]), "=r"(r[2]), "=r"(r[3]) : "r"(a));
}
__device__ __forceinline__ void mmaH(float d[4], const uint32_t a[4],
                                     uint32_t b0, uint32_t b1) {
    asm volatile("mma.sync.aligned.m16n8k16.row.col.f32.f16.f16.f32 "
                 "{%0,%1,%2,%3},{%4,%5,%6,%7},{%8,%9},{%0,%1,%2,%3};"
                 : "+f"(d[0]), "+f"(d[1]), "+f"(d[2]), "+f"(d[3])
                 : "r"(a[0]), "r"(a[1]), "r"(a[2]), "r"(a[3]),
                   "r"(b0), "r"(b1));
}

__device__ void load_weights(__half* W, const float* __restrict__ Whh,
                             const float* __restrict__ Wih, int n0) {
    const int tid = threadIdx.x;
    for (int idx = tid; idx < GT * KTOT; idx += NTHR) {
        int row = idx / KTOT;
        int k = idx - row * KTOT;
        int g = row >> 3, hid = n0 + (row & 7);
        float v = (k < HH) ? Whh[(size_t)(g * HH + hid) * HH + k]
                           : Wih[(size_t)(g * HH + hid) * FF + (k - HH)];
        W[row * WST + k] = __float2half_rn(v);
    }
}

// One LSTM step for this CTA's (128 x 8) tile: quad-buffered cp.async,
// 2-warp named-barrier groups, dual gate buffers, c-prefetch.
__device__ __forceinline__ void lstm_step(
    char* dsm,
    const __half* __restrict__ hcur, __half* __restrict__ hnext,
    float* __restrict__ cbuf, const float* __restrict__ sbias,
    const __half* __restrict__ xptr, int xstride,
    int m0, int n0)
{
    const int tid = threadIdx.x;
    const int lane = tid & 31, warp = tid >> 5;
    const int kw = warp & 1;              // k-split half
    const int wm = warp >> 1;             // m-group 0..3
    const int barid = 1 + wm;

    const uint32_t base = (uint32_t)__cvta_generic_to_shared(dsm);
    const uint32_t Wbase = base;
    const uint32_t Agrp = base + (uint32_t)(AOFF + wm * AGRP);

    // ---- c prefetch (epilogue-only data) ----
    const int hid = tid & 7;
    const int rb = tid >> 3;              // 0..31
    float cpre[4];
#pragma unroll
    for (int it = 0; it < 4; it++)
        cpre[it] = cbuf[(m0 + rb + it * 32) * HH + n0 + hid];

    // ---- loader: group tile = 32 rows x 32 halves; 128 segs of 16B ----
    // seg id = kw*64 + lane*2 + {0,1}; row = id>>2, sc = id&3
    const int id0 = kw * 64 + lane * 2;
    const int row0 = id0 >> 2, sc0 = id0 & 3;
    const int row1 = (id0 + 1) >> 2, sc1 = (id0 + 1) & 3;
    const __half* h0 = hcur + (size_t)(m0 + wm * 32 + row0) * HH + sc0 * 8;
    const __half* h1 = hcur + (size_t)(m0 + wm * 32 + row1) * HH + sc1 * 8;
    const __half* x0 = xptr + (size_t)(m0 + wm * 32 + row0) * xstride + sc0 * 8;
    const __half* x1 = xptr + (size_t)(m0 + wm * 32 + row1) * xstride + sc1 * 8;
    const uint32_t d0 = (uint32_t)(row0 * 80 + sc0 * 16);
    const uint32_t d1 = (uint32_t)(row1 * 80 + sc1 * 16);

    auto issue = [&](int ci) {
        uint32_t sb = Agrp + (uint32_t)((ci & 3) * ASLOT);
        int k0 = ci * KC;
        if (k0 < HH) {
            cpa16(sb + d0, h0 + k0);
            cpa16(sb + d1, h1 + k0);
        } else {
            cpa16(sb + d0, x0 + (k0 - HH));
            cpa16(sb + d1, x1 + (k0 - HH));
        }
        CP_COMMIT();
    };

    // ---- ldmatrix lane addressing ----
    const int lr = lane & 7, lt = lane >> 3;
    const int madd = (lt & 1) * 8;
    const int kadd = (lt >> 1) * 16;      // bytes (8 halves)
    const uint32_t aA0 = (uint32_t)((lr + madd) * 80 + kadd + kw * 32);
    const uint32_t aA1 = aA0 + (uint32_t)(16 * 80);
    const uint32_t bB0 = Wbase
        + (uint32_t)(((lr + madd) * WST) * 2 + kadd + kw * 32);
    const uint32_t bB1 = bB0 + (uint32_t)(16 * WST * 2);

    float acc[2][4][4];
#pragma unroll
    for (int mi = 0; mi < 2; mi++)
#pragma unroll
        for (int ni = 0; ni < 4; ni++)
#pragma unroll
            for (int p = 0; p < 4; p++) acc[mi][ni][p] = 0.0f;

    issue(0); issue(1); issue(2);

#pragma unroll 1
    for (int i = 0; i < NCHUNK; i++) {
        if (i + 3 >= NCHUNK) CP_COMMIT();
        asm volatile("cp.async.wait_group 2;" ::: "memory");
        asm volatile("bar.sync %0, 64;" :: "r"(barid) : "memory");
        if (i + 3 < NCHUNK) issue(i + 3);

        const uint32_t sA = Agrp + (uint32_t)((i & 3) * ASLOT);
        const uint32_t ko = (uint32_t)(i * (KC * 2));   // weight k offset bytes
        uint32_t A0[4], A1[4], B0[4], B1[4];
        ldsm4(A0, sA + aA0);
        ldsm4(A1, sA + aA1);
        ldsm4(B0, bB0 + ko);
        ldsm4(B1, bB1 + ko);
        mmaH(acc[0][0], A0, B0[0], B0[2]);
        mmaH(acc[0][1], A0, B0[1], B0[3]);
        mmaH(acc[0][2], A0, B1[0], B1[2]);
        mmaH(acc[0][3], A0, B1[1], B1[3]);
        mmaH(acc[1][0], A1, B0[0], B0[2]);
        mmaH(acc[1][1], A1, B0[1], B0[3]);
        mmaH(acc[1][2], A1, B1[0], B1[2]);
        mmaH(acc[1][3], A1, B1[1], B1[3]);
    }

    // epilogue: each k-half to its own gate buffer (no merge pass)
    asm volatile("cp.async.wait_group 0;" ::: "memory");
    __syncthreads();
    float (*Gs)[GST]  = (float (*)[GST])(dsm + AOFF);
    float (*Gs2)[GST] = (float (*)[GST])(dsm + GS2OFF);
    float (*Gw)[GST] = kw ? Gs2 : Gs;
    const int wmB = wm * 32;
#pragma unroll
    for (int mi = 0; mi < 2; mi++)
#pragma unroll
        for (int ni = 0; ni < 4; ni++) {
            int r = wmB + mi * 16 + (lane >> 2);
            int c = ni * 8 + (lane & 3) * 2;
            *(float2*)&Gw[r][c]     = make_float2(acc[mi][ni][0], acc[mi][ni][1]);
            *(float2*)&Gw[r + 8][c] = make_float2(acc[mi][ni][2], acc[mi][ni][3]);
        }
    __syncthreads();

    // pointwise LSTM update (1024 elems, 4 per thread), c from prefetch regs
    const float bi = sbias[hid];
    const float bf = sbias[8 + hid];
    const float bg = sbias[16 + hid];
    const float bo = sbias[24 + hid];
#pragma unroll
    for (int it = 0; it < 4; it++) {
        int r = rb + it * 32;
        float iv = Gs[r][hid]      + Gs2[r][hid]      + bi;
        float fv = Gs[r][8 + hid]  + Gs2[r][8 + hid]  + bf;
        float gv = Gs[r][16 + hid] + Gs2[r][16 + hid] + bg;
        float ov = Gs[r][24 + hid] + Gs2[r][24 + hid] + bo;
        int gi = (m0 + r) * HH + n0 + hid;
        float cn = sigm(fv) * cpre[it] + sigm(iv) * tanh_f(gv);
        float hn = sigm(ov) * tanh_f(cn);
        cbuf[gi] = cn;
        hnext[gi] = __float2half_rn(hn);
    }
}

// pred = h @ W_fc^T + b_fc ; 1 batch row per CTA.
__device__ __forceinline__ void pred_step(
    char* dsm, const __half* __restrict__ h,
    const float* __restrict__ Wfc, const float* __restrict__ bfc,
    float* __restrict__ out, int t, int T, int brow)
{
    float* Hs = (float*)(dsm + AOFF);
    const int tid = threadIdx.x;

    // stage h row (1024 halves -> floats): 512 half2, 2 per thread
#pragma unroll
    for (int q = 0; q < 2; q++) {
        int c2 = tid + q * NTHR;
        float2 f = __half22float2(((const __half2*)(h + (size_t)brow * HH))[c2]);
        Hs[c2 * 2]     = f.x;
        Hs[c2 * 2 + 1] = f.y;
    }
    __syncthreads();

    const int warp = tid >> 5, lane = tid & 31;
    for (int f = warp; f < 64; f += 8) {
        const float4* wrow = (const float4*)&Wfc[(size_t)f * HH];
        const float4* hrow = (const float4*)Hs;
        float s = 0.0f;
#pragma unroll 4
        for (int k4 = lane; k4 < 256; k4 += 32) {
            float4 w = wrow[k4];
            float4 hv = hrow[k4];
            s += w.x * hv.x + w.y * hv.y + w.z * hv.z + w.w * hv.w;
        }
#pragma unroll
        for (int off = 16; off; off >>= 1)
            s += __shfl_xor_sync(0xffffffffu, s, off);
        if (lane == 0) {
            float p = s + bfc[f];
            out[(size_t)brow * T * FF + t * FF + f] = p;
            g_x[brow * FF + f] = __float2half_rn(p);
        }
    }
    __syncthreads();
}

__global__ void __launch_bounds__(NTHR, 2) s2s_kernel(
    const float* __restrict__ x_seq,
    const float* __restrict__ Wih_e, const float* __restrict__ Whh_e,
    const float* __restrict__ bih_e, const float* __restrict__ bhh_e,
    const float* __restrict__ Wih_d, const float* __restrict__ Whh_d,
    const float* __restrict__ bih_d, const float* __restrict__ bhh_d,
    const float* __restrict__ Wfc, const float* __restrict__ bfc,
    const int* __restrict__ plen,
    float* __restrict__ out)
{
    extern __shared__ char dsm[];
    const int tid = threadIdx.x;
    const int gb = blockIdx.x >> 7;               // batch group 0/1
    const int cid = blockIdx.x & 127;             // hidden block 0..127
    const int m0 = gb * MB;
    const int n0 = cid * NH;
    const int brow = gb * MB + cid;               // this CTA's pred batch row
    float* sbias = (float*)(dsm + CTRL);

    // Phase 0: encoder weights + biases + group-local x conv / h,c zero
    load_weights((__half*)dsm, Whh_e, Wih_e, n0);
    if (tid < 32)
        sbias[tid] = bih_e[(tid >> 3) * HH + n0 + (tid & 7)]
                   + bhh_e[(tid >> 3) * HH + n0 + (tid & 7)];
    {
        const int gtid = cid * NTHR + tid;
        const int gstr = 128 * NTHR;
        const int n4 = MB * SS * FF / 4;
        const int xb4 = gb * n4;
        for (int i = gtid; i < n4; i += gstr) {
            float4 v = ((const float4*)x_seq)[xb4 + i];
            ((__half2*)g_xs)[(xb4 + i) * 2]     = __floats2half2_rn(v.x, v.y);
            ((__half2*)g_xs)[(xb4 + i) * 2 + 1] = __floats2half2_rn(v.z, v.w);
        }
        uint4 z4 = make_uint4(0, 0, 0, 0);
        const int hb = gb * (MB * HH / 8);
        for (int i = gtid; i < MB * HH / 8; i += gstr) ((uint4*)g_h[0])[hb + i] = z4;
        float4 zf = make_float4(0.f, 0.f, 0.f, 0.f);
        const int cbx = gb * (MB * HH / 4);
        for (int i = gtid; i < MB * HH / 4; i += gstr) ((float4*)g_c)[cbx + i] = zf;
    }
    grid_barrier(gb);

    int cur = 0;
    // ---- encoder ----
#pragma unroll 1
    for (int t = 0; t < SS; t++) {
        lstm_step(dsm, g_h[cur], g_h[cur ^ 1], g_c, sbias,
                  g_xs + (size_t)t * FF, SS * FF, m0, n0);
        grid_barrier(gb);
        cur ^= 1;
    }

    // swap to decoder weights (per-CTA smem, local sync only)
    __syncthreads();
    load_weights((__half*)dsm, Whh_d, Wih_d, n0);
    if (tid < 32)
        sbias[tid] = bih_d[(tid >> 3) * HH + n0 + (tid & 7)]
                   + bhh_d[(tid >> 3) * HH + n0 + (tid & 7)];
    __syncthreads();

    // ---- decoder ----
    const int T = *plen;
#pragma unroll 1
    for (int t = 0; t < T; t++) {
        const __half* xp = (t == 0) ? (g_xs + (size_t)(SS - 1) * FF) : g_x;
        const int xs = (t == 0) ? (SS * FF) : FF;
        lstm_step(dsm, g_h[cur], g_h[cur ^ 1], g_c, sbias,
                  xp, xs, m0, n0);
        grid_barrier(gb);
        cur ^= 1;
        pred_step(dsm, g_h[cur], Wfc, bfc, out, t, T, brow);
        grid_barrier(gb);
    }
}

extern "C" void kernel_launch(void* const* d_in, const int* in_sizes, int n_in,
                              void* d_out, int out_size)
{
    const float* x_seq = (const float*)d_in[0];
    const float* Wih_e = (const float*)d_in[1];
    const float* Whh_e = (const float*)d_in[2];
    const float* bih_e = (const float*)d_in[3];
    const float* bhh_e = (const float*)d_in[4];
    const float* Wih_d = (const float*)d_in[5];
    const float* Whh_d = (const float*)d_in[6];
    const float* bih_d = (const float*)d_in[7];
    const float* bhh_d = (const float*)d_in[8];
    const float* Wfc   = (const float*)d_in[9];
    const float* bfc   = (const float*)d_in[10];
    const int*   plen  = (const int*)d_in[11];
    float* out = (float*)d_out;

    cudaFuncSetAttribute(s2s_kernel,
                         cudaFuncAttributeMaxDynamicSharedMemorySize, SMEM_BYTES);
    s2s_kernel<<<NCTA, NTHR, SMEM_BYTES>>>(x_seq, Wih_e, Whh_e, bih_e, bhh_e,
                                           Wih_d, Whh_d, bih_d, bhh_d,
                                           Wfc, bfc, plen, out);
}

// round 14
// speedup vs baseline: 1.4562x; 1.4562x over previous
#include <cuda_runtime.h>
#include <cuda_fp16.h>
#include <cstdint>

// Shapes (fixed)
#define BB 256
#define SS 512
#define FF 64
#define HH 1024

#define NCTA 128    // 2 batch-groups x 64 hidden-blocks
#define NTHR 512    // 16 warps: 4 m-groups x (2n x 2k-split)
#define MB 128
#define NH 16
#define GT 64
#define KC 64
#define KTOT (HH + FF)          // 1088
#define NCHUNK (KTOT / KC)      // 17
#define NSTG 4                  // per-group A slots (quad buffer)

#define WST 1096
#define GST 68                  // gate buffer row stride (floats); 32 rows/buffer

#define WBYTES (GT * WST * 2)           // 140288
#define ASLOT 4608                      // 32 rows x 144B
#define AGRP (NSTG * ASLOT)             // 18432 per m-group
#define ABYTES (4 * AGRP)               // 73728
#define AOFF WBYTES
#define GBUF 8704                       // 32 * 68 * 4 per gate half-buffer
#define CTRL (WBYTES + ABYTES)          // 214016
#define SMEM_BYTES (CTRL + 256)

// Persistent state (no allocations allowed)
__device__ __half g_h[2][BB * HH];
__device__ float  g_c[BB * HH];
__device__ __half g_x[BB * FF];
__device__ __half g_xs[BB * SS * FF];
__device__ unsigned g_bar_cnt[2];
__device__ unsigned g_bar_gen[2];

// two-group grid barrier (batch halves are fully independent)
__device__ __forceinline__ void grid_barrier(int grp) {
    __syncthreads();
    if (threadIdx.x == 0) {
        __threadfence();
        unsigned gen = *(volatile unsigned*)&g_bar_gen[grp];
        if (atomicAdd(&g_bar_cnt[grp], 1u) == 63u) {
            atomicExch(&g_bar_cnt[grp], 0u);
            __threadfence();
            atomicAdd(&g_bar_gen[grp], 1u);
        } else {
            while (*(volatile unsigned*)&g_bar_gen[grp] == gen) { }
        }
        __threadfence();
    }
    __syncthreads();
}

// fast activations: tanh.approx (1 MUFU); sigmoid via tanh identity
__device__ __forceinline__ float tanh_fast(float x) {
    float r;
    asm("tanh.approx.f32 %0, %1;" : "=f"(r) : "f"(x));
    return r;
}
__device__ __forceinline__ float sigm_fast(float x) {
    return fmaf(tanh_fast(0.5f * x), 0.5f, 0.5f);
}

__device__ __forceinline__ void cpa16(uint32_t s, const void* g) {
    asm volatile("cp.async.cg.shared.global [%0], [%1], 16;" :: "r"(s), "l"(g));
}
#define CP_COMMIT() asm volatile("cp.async.commit_group;" ::: "memory")
__device__ __forceinline__ void ldsm4(uint32_t r[4], uint32_t a) {
    asm volatile("ldmatrix.sync.aligned.m8n8.x4.shared.b16 {%0,%1,%2,%3}, [%4];"
                 : "=r"(r[0]), "=r"(r[1]), "=r"(r[2]), "=r"(r[3]) : "r"(a));
}
__device__ __forceinline__ void mmaH(float d[4], const uint32_t a[4],
                                     uint32_t b0, uint32_t b1) {
    asm volatile("mma.sync.aligned.m16n8k16.row.col.f32.f16.f16.f32 "
                 "{%0,%1,%2,%3},{%4,%5,%6,%7},{%8,%9},{%0,%1,%2,%3};"
                 : "+f"(d[0]), "+f"(d[1]), "+f"(d[2]), "+f"(d[3])
                 : "r"(a[0]), "r"(a[1]), "r"(a[2]), "r"(a[3]),
                   "r"(b0), "r"(b1));
}

__device__ void load_weights(__half* W, const float* __restrict__ Whh,
                             const float* __restrict__ Wih, int n0) {
    const int tid = threadIdx.x;
    for (int idx = tid; idx < GT * KTOT; idx += NTHR) {
        int row = idx / KTOT;
        int k = idx - row * KTOT;
        int g = row >> 4, hid = n0 + (row & 15);
        float v = (k < HH) ? Whh[(size_t)(g * HH + hid) * HH + k]
                           : Wih[(size_t)(g * HH + hid) * FF + (k - HH)];
        W[row * WST + k] = __float2half_rn(v);
    }
}

// One LSTM step: quad-buffered cp.async staging, named-barrier group sync,
// per-m-group gate buffers + epilogue (no CTA-wide syncs), c-prefetch.
__device__ __forceinline__ void lstm_step(
    char* dsm,
    const __half* __restrict__ hcur, __half* __restrict__ hnext,
    float* __restrict__ cbuf, const float* __restrict__ sbias,
    const __half* __restrict__ xptr, int xstride,
    int m0, int n0)
{
    const int tid = threadIdx.x;
    const int lane = tid & 31, warp = tid >> 5;
    const int kw = warp >> 3;
    const int wm = (warp >> 1) & 3;
    const int wn = warp & 1;
    const int barid = 1 + wm;

    const uint32_t base = (uint32_t)__cvta_generic_to_shared(dsm);
    const uint32_t Wbase = base;
    const uint32_t Agrp = base + (uint32_t)(AOFF + wm * AGRP);

    // ---- per-m-group pointwise mapping + c prefetch ----
    const int lt128 = (kw * 2 + wn) * 32 + lane;   // 0..127 within m-group
    const int hid = lt128 & 15;
    const int rb2 = lt128 >> 4;                    // 0..7
    float cpre[4];
#pragma unroll
    for (int it = 0; it < 4; it++)
        cpre[it] = cbuf[(m0 + wm * 32 + rb2 + it * 8) * HH + n0 + hid];

    // loader: this warp's quarter of the group's 32x64 tile
    const int q = (warp & 1) | ((warp >> 3) << 1);
    const int id0 = q * 64 + lane * 2;
    const int row0 = id0 >> 3, ks0 = id0 & 7;
    const int row1 = (id0 + 1) >> 3, ks1 = (id0 + 1) & 7;
    const __half* h0 = hcur + (size_t)(m0 + wm * 32 + row0) * HH + ks0 * 8;
    const __half* h1 = hcur + (size_t)(m0 + wm * 32 + row1) * HH + ks1 * 8;
    const __half* x0 = xptr + (size_t)(m0 + wm * 32 + row0) * xstride + ks0 * 8;
    const __half* x1 = xptr + (size_t)(m0 + wm * 32 + row1) * xstride + ks1 * 8;
    const uint32_t d0 = (uint32_t)(row0 * 144 + ks0 * 16);
    const uint32_t d1 = (uint32_t)(row1 * 144 + ks1 * 16);

    auto issue = [&](int ci) {
        uint32_t sb = Agrp + (uint32_t)((ci & 3) * ASLOT);
        int k0 = ci * KC;
        if (k0 < HH) {
            cpa16(sb + d0, h0 + k0);
            cpa16(sb + d1, h1 + k0);
        } else {
            cpa16(sb + d0, x0 + (k0 - HH));
            cpa16(sb + d1, x1 + (k0 - HH));
        }
        CP_COMMIT();
    };

    // ldmatrix lane addressing
    const int lr = lane & 7, lt = lane >> 3;
    const int madd = (lt & 1) * 8;
    const uint32_t aA0 = (uint32_t)((lr + madd) * 144 + (lt >> 1) * 16);
    const uint32_t aA1 = aA0 + (uint32_t)(16 * 144);
    const uint32_t bB0 = Wbase
        + (uint32_t)(((wn * 32 + lr + madd) * WST + (lt >> 1) * 8) * 2);
    const uint32_t bB1 = bB0 + (uint32_t)(16 * WST * 2);

    float acc[2][4][4];
#pragma unroll
    for (int mi = 0; mi < 2; mi++)
#pragma unroll
        for (int ni = 0; ni < 4; ni++)
#pragma unroll
            for (int p = 0; p < 4; p++) acc[mi][ni][p] = 0.0f;

    issue(0); issue(1); issue(2);

#pragma unroll 1
    for (int i = 0; i < NCHUNK; i++) {
        if (i + 3 >= NCHUNK) CP_COMMIT();
        asm volatile("cp.async.wait_group 2;" ::: "memory");
        asm volatile("bar.sync %0, 128;" :: "r"(barid) : "memory");
        if (i + 3 < NCHUNK) issue(i + 3);

        const uint32_t sA = Agrp + (uint32_t)((i & 3) * ASLOT);
        const uint32_t ko = (uint32_t)(i * (KC * 2));
#pragma unroll
        for (int kb2 = 0; kb2 < 2; kb2++) {
            const int kb = kw * 2 + kb2;
            uint32_t A0[4], A1[4], B0[4], B1[4];
            ldsm4(A0, sA + aA0 + kb * 32);
            ldsm4(A1, sA + aA1 + kb * 32);
            ldsm4(B0, bB0 + ko + kb * 32);
            ldsm4(B1, bB1 + ko + kb * 32);
            mmaH(acc[0][0], A0, B0[0], B0[2]);
            mmaH(acc[0][1], A0, B0[1], B0[3]);
            mmaH(acc[0][2], A0, B1[0], B1[2]);
            mmaH(acc[0][3], A0, B1[1], B1[3]);
            mmaH(acc[1][0], A1, B0[0], B0[2]);
            mmaH(acc[1][1], A1, B0[1], B0[3]);
            mmaH(acc[1][2], A1, B1[0], B1[2]);
            mmaH(acc[1][3], A1, B1[1], B1[3]);
        }
    }

    // ---- per-m-group epilogue: drain own cp.asyncs, group-sync, store, sync,
    //      pointwise on this group's 32 rows. No CTA-wide barrier here. ----
    asm volatile("cp.async.wait_group 0;" ::: "memory");
    asm volatile("bar.sync %0, 128;" :: "r"(barid) : "memory");

    float (*G0)[GST] = (float (*)[GST])(dsm + AOFF + wm * AGRP);
    float (*G1)[GST] = (float (*)[GST])(dsm + AOFF + wm * AGRP + GBUF);
    float (*Gw)[GST] = kw ? G1 : G0;
#pragma unroll
    for (int mi = 0; mi < 2; mi++)
#pragma unroll
        for (int ni = 0; ni < 4; ni++) {
            int r = mi * 16 + (lane >> 2);          // local row 0..31
            int c = wn * 32 + ni * 8 + (lane & 3) * 2;
            *(float2*)&Gw[r][c]     = make_float2(acc[mi][ni][0], acc[mi][ni][1]);
            *(float2*)&Gw[r + 8][c] = make_float2(acc[mi][ni][2], acc[mi][ni][3]);
        }
    asm volatile("bar.sync %0, 128;" :: "r"(barid) : "memory");

    // pointwise: this m-group's 32 rows x 16 hid (512 elems, 4 per thread)
    const float bi = sbias[hid];
    const float bf = sbias[16 + hid];
    const float bg = sbias[32 + hid];
    const float bo = sbias[48 + hid];
#pragma unroll
    for (int it = 0; it < 4; it++) {
        int r = rb2 + it * 8;                      // local row
        float iv = G0[r][hid]      + G1[r][hid]      + bi;
        float fv = G0[r][16 + hid] + G1[r][16 + hid] + bf;
        float gv = G0[r][32 + hid] + G1[r][32 + hid] + bg;
        float ov = G0[r][48 + hid] + G1[r][48 + hid] + bo;
        int gi = (m0 + wm * 32 + r) * HH + n0 + hid;
        float cn = sigm_fast(fv) * cpre[it] + sigm_fast(iv) * tanh_fast(gv);
        float hn = sigm_fast(ov) * tanh_fast(cn);
        cbuf[gi] = cn;
        hnext[gi] = __float2half_rn(hn);
    }
}

// pred = h @ W_fc^T + b_fc ; out[b,t,:] fp32, g_x fp16 feed.
__device__ __forceinline__ void pred_step(
    char* dsm, const __half* __restrict__ h,
    const float* __restrict__ Wfc, const float* __restrict__ bfc,
    float* __restrict__ out, int t, int T)
{
    float (*Hs)[HH] = (float (*)[HH])(dsm + AOFF);
    const int tid = threadIdx.x;
    const int pr0 = blockIdx.x * 2;

#pragma unroll
    for (int q = 0; q < 2; q++) {
        int idx = tid + q * NTHR;
        int r = idx >> 9, c2 = idx & 511;
        float2 f = __half22float2(((const __half2*)(h + (size_t)(pr0 + r) * HH))[c2]);
        Hs[r][c2 * 2]     = f.x;
        Hs[r][c2 * 2 + 1] = f.y;
    }
    __syncthreads();

    const int warp = tid >> 5, lane = tid & 31;
    for (int oi = warp; oi < 128; oi += 16) {
        int r = oi >> 6, f = oi & 63;
        const float4* wrow = (const float4*)&Wfc[(size_t)f * HH];
        const float4* hrow = (const float4*)&Hs[r][0];
        float s = 0.0f;
#pragma unroll 4
        for (int k4 = lane; k4 < 256; k4 += 32) {
            float4 w = wrow[k4];
            float4 hv = hrow[k4];
            s += w.x * hv.x + w.y * hv.y + w.z * hv.z + w.w * hv.w;
        }
#pragma unroll
        for (int off = 16; off; off >>= 1)
            s += __shfl_xor_sync(0xffffffffu, s, off);
        if (lane == 0) {
            float p = s + bfc[f];
            int b = pr0 + r;
            out[(size_t)b * T * FF + t * FF + f] = p;
            g_x[b * FF + f] = __float2half_rn(p);
        }
    }
    __syncthreads();
}

__global__ void __launch_bounds__(NTHR, 1) s2s_kernel(
    const float* __restrict__ x_seq,
    const float* __restrict__ Wih_e, const float* __restrict__ Whh_e,
    const float* __restrict__ bih_e, const float* __restrict__ bhh_e,
    const float* __restrict__ Wih_d, const float* __restrict__ Whh_d,
    const float* __restrict__ bih_d, const float* __restrict__ bhh_d,
    const float* __restrict__ Wfc, const float* __restrict__ bfc,
    const int* __restrict__ plen,
    float* __restrict__ out)
{
    extern __shared__ char dsm[];
    const int tid = threadIdx.x;
    const int gb = blockIdx.x >> 6;
    const int cid = blockIdx.x & 63;
    const int m0 = gb * MB;
    const int n0 = cid * NH;
    float* sbias = (float*)(dsm + CTRL);

    // Phase 0: encoder weights + biases + group-local x conv / h,c zero
    load_weights((__half*)dsm, Whh_e, Wih_e, n0);
    if (tid < 64)
        sbias[tid] = bih_e[(tid >> 4) * HH + n0 + (tid & 15)]
                   + bhh_e[(tid >> 4) * HH + n0 + (tid & 15)];
    {
        const int gtid = cid * NTHR + tid;
        const int gstr = 64 * NTHR;
        const int n4 = MB * SS * FF / 4;
        const int xb4 = gb * n4;
        for (int i = gtid; i < n4; i += gstr) {
            float4 v = ((const float4*)x_seq)[xb4 + i];
            ((__half2*)g_xs)[(xb4 + i) * 2]     = __floats2half2_rn(v.x, v.y);
            ((__half2*)g_xs)[(xb4 + i) * 2 + 1] = __floats2half2_rn(v.z, v.w);
        }
        uint4 z4 = make_uint4(0, 0, 0, 0);
        const int hb = gb * (MB * HH / 8);
        for (int i = gtid; i < MB * HH / 8; i += gstr) ((uint4*)g_h[0])[hb + i] = z4;
        float4 zf = make_float4(0.f, 0.f, 0.f, 0.f);
        const int cbx = gb * (MB * HH / 4);
        for (int i = gtid; i < MB * HH / 4; i += gstr) ((float4*)g_c)[cbx + i] = zf;
    }
    grid_barrier(gb);

    int cur = 0;
    // ---- encoder ----
#pragma unroll 1
    for (int t = 0; t < SS; t++) {
        lstm_step(dsm, g_h[cur], g_h[cur ^ 1], g_c, sbias,
                  g_xs + (size_t)t * FF, SS * FF, m0, n0);
        grid_barrier(gb);
        cur ^= 1;
    }

    // swap to decoder weights (per-CTA smem, local sync only)
    __syncthreads();
    load_weights((__half*)dsm, Whh_d, Wih_d, n0);
    if (tid < 64)
        sbias[tid] = bih_d[(tid >> 4) * HH + n0 + (tid & 15)]
                   + bhh_d[(tid >> 4) * HH + n0 + (tid & 15)];
    __syncthreads();

    // ---- decoder ----
    const int T = *plen;
#pragma unroll 1
    for (int t = 0; t < T; t++) {
        const __half* xp = (t == 0) ? (g_xs + (size_t)(SS - 1) * FF) : g_x;
        const int xs = (t == 0) ? (SS * FF) : FF;
        lstm_step(dsm, g_h[cur], g_h[cur ^ 1], g_c, sbias,
                  xp, xs, m0, n0);
        grid_barrier(gb);
        cur ^= 1;
        pred_step(dsm, g_h[cur], Wfc, bfc, out, t, T);
        grid_barrier(gb);
    }
}

extern "C" void kernel_launch(void* const* d_in, const int* in_sizes, int n_in,
                              void* d_out, int out_size)
{
    const float* x_seq = (const float*)d_in[0];
    const float* Wih_e = (const float*)d_in[1];
    const float* Whh_e = (const float*)d_in[2];
    const float* bih_e = (const float*)d_in[3];
    const float* bhh_e = (const float*)d_in[4];
    const float* Wih_d = (const float*)d_in[5];
    const float* Whh_d = (const float*)d_in[6];
    const float* bih_d = (const float*)d_in[7];
    const float* bhh_d = (const float*)d_in[8];
    const float* Wfc   = (const float*)d_in[9];
    const float* bfc   = (const float*)d_in[10];
    const int*   plen  = (const int*)d_in[11];
    float* out = (float*)d_out;

    cudaFuncSetAttribute(s2s_kernel,
                         cudaFuncAttributeMaxDynamicSharedMemorySize, SMEM_BYTES);
    s2s_kernel<<<NCTA, NTHR, SMEM_BYTES>>>(x_seq, Wih_e, Whh_e, bih_e, bhh_e,
                                           Wih_d, Whh_d, bih_d, bhh_d,
                                           Wfc, bfc, plen, out);
}